// round 15
// baseline (speedup 1.0000x reference)
#include <cuda_runtime.h>
#include <cuda_bf16.h>
#include <cstdint>
#include <cmath>

#define BB 4
#define TT 2048
#define HH 8
#define DD 96
#define KDIM 768
#define BHN 32
#define SSTR 98

// Fragment-order scratch (uint4 per lane = two adjacent B-frags where paired)
__device__ uint4 g_qhi[BHN*128*6*32], g_qlo[BHN*128*6*32];   // Q A-frags [bh][t16][kt6][lane]
__device__ uint4 g_khi[BHN*32*6*4*32], g_klo[BHN*32*6*4*32]; // K B-fragpairs [bh][chunk][kt6][ktpair4][lane]
__device__ uint4 g_vhi[BHN*128*6*32], g_vlo[BHN*128*6*32];   // V B-fragpairs [bh][kt16][ndpair6][lane]
__device__ uint4 g_oahi[512*48*32], g_oalo[512*48*32];       // O A-frags [t16 512][kt48][lane]
__device__ uint4 g_wuhi[48*48*32], g_wulo[48*48*32];         // Wu B-fragpairs [kt48][ntpair48][lane]
__device__ uint4 g_wqh[108*32], g_wql[108*32];               // Wq/Wk/Wv B-fragpairs [mat3][kt6][ntpair6][lane]

__device__ __forceinline__ float fexp2(float x){ float y; asm("ex2.approx.ftz.f32 %0, %1;" : "=f"(y):"f"(x)); return y; }
__device__ __forceinline__ uint32_t smem_u32(const void* p){ uint32_t a; asm("{.reg .u64 t; cvta.to.shared.u64 t,%1; cvt.u32.u64 %0,t;}":"=r"(a):"l"(p)); return a; }

// pack (a,b) -> bf16x2 {lo16=a, hi16=b}
__device__ __forceinline__ uint32_t bfhi(float a, float b){
    uint32_t r; asm("cvt.rn.bf16x2.f32 %0, %1, %2;" : "=r"(r) : "f"(b), "f"(a)); return r;
}
__device__ __forceinline__ uint32_t bflo(float a, float b, uint32_t h){
    float ah = __uint_as_float(h<<16);
    float bh = __uint_as_float(h & 0xffff0000u);
    return bfhi(a-ah, b-bh);
}

#define MMA(D,A,B0,B1) asm volatile( \
  "mma.sync.aligned.m16n8k16.row.col.f32.bf16.bf16.f32 " \
  "{%0,%1,%2,%3}, {%4,%5,%6,%7}, {%8,%9}, {%0,%1,%2,%3};" \
  : "+f"((D)[0]), "+f"((D)[1]), "+f"((D)[2]), "+f"((D)[3]) \
  : "r"((A).x), "r"((A).y), "r"((A).z), "r"((A).w), "r"(B0), "r"(B1))

#define CP16(dst,src) asm volatile("cp.async.cg.shared.global [%0], [%1], 16;\n" :: "r"(dst), "l"(src))
#define CP_COMMIT()   asm volatile("cp.async.commit_group;\n" ::: "memory")
#define CP_WAIT(n)    asm volatile("cp.async.wait_group %0;\n" :: "n"(n) : "memory")

// ---------------- Kernel 0: all weights -> B-fragpair planes -----------------
__global__ __launch_bounds__(256) void wprep_kernel(
    const float* __restrict__ Wq, const float* __restrict__ Wk,
    const float* __restrict__ Wv, const float* __restrict__ Wu, float qscale)
{
    int wid = blockIdx.x*8 + (threadIdx.x>>5);
    int lane = threadIdx.x&31;
    if (wid < 2304){          // Wu: kt48 x ntpair48
        int kt = wid/48, ntp = wid - kt*48;
        int i = kt*16 + (lane&3)*2;
        int o0 = (2*ntp)*8 + (lane>>2);
        const float* r0 = Wu + (size_t)o0*768 + i;
        const float* r1 = r0 + 8*768;
        uint4 hi, lo;
        hi.x=bfhi(r0[0],r0[1]); hi.y=bfhi(r0[8],r0[9]);
        hi.z=bfhi(r1[0],r1[1]); hi.w=bfhi(r1[8],r1[9]);
        lo.x=bflo(r0[0],r0[1],hi.x); lo.y=bflo(r0[8],r0[9],hi.y);
        lo.z=bflo(r1[0],r1[1],hi.z); lo.w=bflo(r1[8],r1[9],hi.w);
        size_t idx = (size_t)wid*32 + lane;
        g_wuhi[idx]=hi; g_wulo[idx]=lo;
    } else if (wid < 2412){   // Wq/Wk/Wv: mat3 x kt6 x ntpair6
        int id = wid - 2304;
        int mat = id/36, r = id - mat*36;
        int kt = r/6, p = r - kt*6;
        const float* W = (mat==0)?Wq:(mat==1)?Wk:Wv;
        float s = (mat==0)? qscale : 1.0f;
        int i  = kt*16 + (lane&3)*2;
        int o0 = (2*p)*8 + (lane>>2);
        const float* r0 = W + (size_t)o0*96 + i;
        const float* r1 = r0 + 8*96;
        float a0=r0[0]*s, a1=r0[1]*s, b0=r0[8]*s, b1=r0[9]*s;
        float c0=r1[0]*s, c1=r1[1]*s, d0=r1[8]*s, d1=r1[9]*s;
        uint4 hi, lo;
        hi.x=bfhi(a0,a1); hi.y=bfhi(b0,b1);
        hi.z=bfhi(c0,c1); hi.w=bfhi(d0,d1);
        lo.x=bflo(a0,a1,hi.x); lo.y=bflo(b0,b1,hi.y);
        lo.z=bflo(c0,c1,hi.z); lo.w=bflo(d0,d1,hi.w);
        g_wqh[id*32+lane]=hi; g_wql[id*32+lane]=lo;
    }
}

// ---------------- Kernel 1: fused QKV projection via mma ---------------------
__global__ __launch_bounds__(256) void qkv_kernel(const float* __restrict__ x)
{
    extern __shared__ float sm1[];
    float* sX = sm1;            // [64][100]
    float* sS = sm1 + 6400;     // [64][SSTR] (V only)
    const int tid = threadIdx.x;
    const int h = blockIdx.y;
    const int t0g = blockIdx.x * 64;
    const int b = t0g >> 11, tl0 = t0g & 2047;
    const int bh = b*HH + h;

    for (int i=tid;i<1536;i+=256){ int r=i/24,q4=i-r*24;
        ((uint4*)sX)[r*25+q4] = *(const uint4*)(x + (size_t)(t0g+r)*768 + h*96 + q4*4); }
    __syncthreads();

    const int lane=tid&31, w=tid>>5;
    const int gr=lane>>2, kk=(lane&3)*2;
    const int rowb = (w&3)*16;
    const int pb   = (w>>2)*3;

    uint4 ah[6], al[6];
    #pragma unroll
    for (int kt=0;kt<6;kt++){
        const float* r0 = sX + (rowb+gr)*100 + kt*16 + kk;
        const float* r1 = r0 + 800;
        float a0=r0[0], a1=r0[1], b0=r1[0], b1=r1[1];
        float c0=r0[8], c1=r0[9], d0=r1[8], d1=r1[9];
        ah[kt].x=bfhi(a0,a1); ah[kt].y=bfhi(b0,b1);
        ah[kt].z=bfhi(c0,c1); ah[kt].w=bfhi(d0,d1);
        al[kt].x=bflo(a0,a1,ah[kt].x); al[kt].y=bflo(b0,b1,ah[kt].y);
        al[kt].z=bflo(c0,c1,ah[kt].z); al[kt].w=bflo(d0,d1,ah[kt].w);
    }

    #pragma unroll
    for (int mat=0; mat<3; mat++){
        float D[6][4];
        #pragma unroll
        for (int n=0;n<6;n++){
            #pragma unroll
            for (int i=0;i<4;i++) D[n][i]=0.f; }

        #pragma unroll
        for (int kt=0;kt<6;kt++){
            uint4 bh4[3], bl4[3];
            #pragma unroll
            for (int p=0;p<3;p++){
                int idx = (mat*36 + kt*6 + pb + p)*32 + lane;
                bh4[p]=g_wqh[idx]; bl4[p]=g_wql[idx];
            }
            uint4 a = ah[kt];
            #pragma unroll
            for (int p=0;p<3;p++){ MMA(D[2*p],a,bh4[p].x,bh4[p].y); MMA(D[2*p+1],a,bh4[p].z,bh4[p].w); }
            #pragma unroll
            for (int p=0;p<3;p++){ MMA(D[2*p],a,bl4[p].x,bl4[p].y); MMA(D[2*p+1],a,bl4[p].z,bl4[p].w); }
            a = al[kt];
            #pragma unroll
            for (int p=0;p<3;p++){ MMA(D[2*p],a,bh4[p].x,bh4[p].y); MMA(D[2*p+1],a,bh4[p].z,bh4[p].w); }
        }

        if (mat==0){
            size_t qi = ((size_t)(bh*128 + (tl0>>4) + (w&3))*6)*32 + lane;
            #pragma unroll
            for (int p=0;p<3;p++){
                int kt = pb + p;
                uint4 hi, lo;
                hi.x=bfhi(D[2*p][0],D[2*p][1]);     hi.y=bfhi(D[2*p][2],D[2*p][3]);
                hi.z=bfhi(D[2*p+1][0],D[2*p+1][1]); hi.w=bfhi(D[2*p+1][2],D[2*p+1][3]);
                lo.x=bflo(D[2*p][0],D[2*p][1],hi.x);     lo.y=bflo(D[2*p][2],D[2*p][3],hi.y);
                lo.z=bflo(D[2*p+1][0],D[2*p+1][1],hi.z); lo.w=bflo(D[2*p+1][2],D[2*p+1][3],hi.w);
                g_qhi[qi + kt*32]=hi; g_qlo[qi + kt*32]=lo;
            }
        } else if (mat==1){
            int chunk = tl0>>6, kp = w&3;
            size_t ki = ((size_t)(bh*32+chunk)*24)*32 + lane;
            #pragma unroll
            for (int p=0;p<3;p++){
                int kt = pb + p;
                uint4 hi, lo;
                hi.x=bfhi(D[2*p][0],D[2*p][1]);
                hi.y=bfhi(D[2*p+1][0],D[2*p+1][1]);
                hi.z=bfhi(D[2*p][2],D[2*p][3]);
                hi.w=bfhi(D[2*p+1][2],D[2*p+1][3]);
                lo.x=bflo(D[2*p][0],D[2*p][1],hi.x);     lo.y=bflo(D[2*p+1][0],D[2*p+1][1],hi.y);
                lo.z=bflo(D[2*p][2],D[2*p][3],hi.z);     lo.w=bflo(D[2*p+1][2],D[2*p+1][3],hi.w);
                g_khi[ki + (kt*4+kp)*32]=hi; g_klo[ki + (kt*4+kp)*32]=lo;
            }
        } else {
            #pragma unroll
            for (int ln=0;ln<6;ln++){
                int ng  = pb*2 + ln;
                int col = ng*8 + kk;
                int row = rowb + gr;
                *(float2*)(sS + row*SSTR + col)     = make_float2(D[ln][0], D[ln][1]);
                *(float2*)(sS + (row+8)*SSTR + col) = make_float2(D[ln][2], D[ln][3]);
            }
            __syncthreads();
            int ktile=w&3, plane=w>>2;
            const float* Rb = sS + (ktile*16+kk)*SSTR;
            uint4* dst = (plane?g_vlo:g_vhi) + ((size_t)(bh*128 + (tl0>>4) + ktile)*6)*32 + lane;
            #pragma unroll
            for (int p=0;p<6;p++){
                int d0=p*16+gr, d1=p*16+8+gr;
                uint4 u;
                uint32_t hx=bfhi(Rb[d0],Rb[SSTR+d0]), hy=bfhi(Rb[8*SSTR+d0],Rb[9*SSTR+d0]);
                uint32_t hz=bfhi(Rb[d1],Rb[SSTR+d1]), hw=bfhi(Rb[8*SSTR+d1],Rb[9*SSTR+d1]);
                if (plane){
                    u.x=bflo(Rb[d0],Rb[SSTR+d0],hx); u.y=bflo(Rb[8*SSTR+d0],Rb[9*SSTR+d0],hy);
                    u.z=bflo(Rb[d1],Rb[SSTR+d1],hz); u.w=bflo(Rb[8*SSTR+d1],Rb[9*SSTR+d1],hw);
                } else { u.x=hx; u.y=hy; u.z=hz; u.w=hw; }
                dst[p*32]=u;
            }
        }
    }
}

// ---------------- Kernel 2: FA2 mma.sync; K double-buf, V single-buf ---------
#define SHIFT 12.0f

__global__ __launch_bounds__(128,3) void attn_kernel()
{
    extern __shared__ uint4 sbuf[];
    const int tid = threadIdx.x, lane = tid&31, w = tid>>5;
    const int qt = blockIdx.x & 31, h = (blockIdx.x>>5)&7, b = blockIdx.x>>8;
    const int bh = b*HH + h;
    const uint32_t sb32 = smem_u32(sbuf);

    auto issueK = [&](int c, int buf){
        const uint4* pKh = g_khi + (size_t)(bh*32 + c)*768;
        const uint4* pKl = g_klo + (size_t)(bh*32 + c)*768;
        uint32_t base = sb32 + buf*24576;
        #pragma unroll
        for (int i=0;i<6;i++){
            int j = tid + i*128;
            CP16(base + j*16,       pKh + j);
            CP16(base + (768+j)*16, pKl + j);
        }
    };
    auto issueV = [&](int c){
        const uint4* pVh = g_vhi + (size_t)(bh*128 + c*4)*192;
        const uint4* pVl = g_vlo + (size_t)(bh*128 + c*4)*192;
        uint32_t base = sb32 + 49152;
        #pragma unroll
        for (int i=0;i<6;i++){
            int j = tid + i*128;
            CP16(base + j*16,       pVh + j);
            CP16(base + (768+j)*16, pVl + j);
        }
    };

    uint4 qh[6], ql[6];
    {
        const size_t qb = ((size_t)(bh*128 + qt*4 + w)*6)*32 + lane;
        #pragma unroll
        for (int kt=0;kt<6;kt++){ qh[kt]=g_qhi[qb+kt*32]; ql[kt]=g_qlo[qb+kt*32]; }
    }

    float O[12][4];
    #pragma unroll
    for (int n=0;n<12;n++){
        #pragma unroll
        for (int i=0;i<4;i++) O[n][i]=0.f; }
    float l0=0.f, l1=0.f;

    issueK(0,0); CP_COMMIT();
    issueV(0);   CP_COMMIT();
    issueK(1,1); CP_COMMIT();

    for (int c=0;c<32;c++){
        if (c<31) CP_WAIT(2); else CP_WAIT(1);    // K(c) ready
        __syncthreads();

        const uint4* Kb = sbuf + (c&1)*1536;
        const uint4* sKh4 = Kb;
        const uint4* sKl4 = Kb + 768;

        float S[8][4];
        #pragma unroll
        for (int n=0;n<8;n++){
            #pragma unroll
            for (int i=0;i<4;i++) S[n][i]=0.f; }
        #pragma unroll
        for (int kt=0;kt<6;kt++){
            uint4 kh[4], kl[4];
            #pragma unroll
            for (int p=0;p<4;p++){ kh[p]=sKh4[(kt*4+p)*32+lane]; kl[p]=sKl4[(kt*4+p)*32+lane]; }
            uint4 aq = qh[kt];
            #pragma unroll
            for (int p=0;p<4;p++){ MMA(S[2*p],aq,kh[p].x,kh[p].y); MMA(S[2*p+1],aq,kh[p].z,kh[p].w); }
            #pragma unroll
            for (int p=0;p<4;p++){ MMA(S[2*p],aq,kl[p].x,kl[p].y); MMA(S[2*p+1],aq,kl[p].z,kl[p].w); }
            aq = ql[kt];
            #pragma unroll
            for (int p=0;p<4;p++){ MMA(S[2*p],aq,kh[p].x,kh[p].y); MMA(S[2*p+1],aq,kh[p].z,kh[p].w); }
        }

        #pragma unroll
        for (int n=0;n<8;n++){
            S[n][0]=fexp2(S[n][0]-SHIFT); S[n][1]=fexp2(S[n][1]-SHIFT);
            S[n][2]=fexp2(S[n][2]-SHIFT); S[n][3]=fexp2(S[n][3]-SHIFT);
            l0 += S[n][0]+S[n][1]; l1 += S[n][2]+S[n][3];
        }

        uint4 ph[4], pl[4];
        #pragma unroll
        for (int ks=0;ks<4;ks++){
            ph[ks].x = bfhi(S[2*ks][0],  S[2*ks][1]);
            ph[ks].y = bfhi(S[2*ks][2],  S[2*ks][3]);
            ph[ks].z = bfhi(S[2*ks+1][0],S[2*ks+1][1]);
            ph[ks].w = bfhi(S[2*ks+1][2],S[2*ks+1][3]);
            pl[ks].x = bflo(S[2*ks][0],  S[2*ks][1],  ph[ks].x);
            pl[ks].y = bflo(S[2*ks][2],  S[2*ks][3],  ph[ks].y);
            pl[ks].z = bflo(S[2*ks+1][0],S[2*ks+1][1],ph[ks].z);
            pl[ks].w = bflo(S[2*ks+1][2],S[2*ks+1][3],ph[ks].w);
        }

        if (c<31) CP_WAIT(1); else CP_WAIT(0);    // V(c) ready
        __syncthreads();   // also proves all warps done reading K buf (c&1)

        // early K prefetch: buffer (c&1) free now (all warps' S reads done)
        if (c<30){ issueK(c+2, c&1); CP_COMMIT(); }

        const uint4* sVh4 = sbuf + 3072;
        const uint4* sVl4 = sbuf + 3840;
        #pragma unroll
        for (int ks=0;ks<4;ks++){
            uint4 vh[6], vl[6];
            #pragma unroll
            for (int p=0;p<6;p++){ vh[p]=sVh4[(ks*6+p)*32+lane]; vl[p]=sVl4[(ks*6+p)*32+lane]; }
            uint4 a = ph[ks];
            #pragma unroll
            for (int p=0;p<6;p++){ MMA(O[2*p],a,vh[p].x,vh[p].y); MMA(O[2*p+1],a,vh[p].z,vh[p].w); }
            #pragma unroll
            for (int p=0;p<6;p++){ MMA(O[2*p],a,vl[p].x,vl[p].y); MMA(O[2*p+1],a,vl[p].z,vl[p].w); }
            a = pl[ks];
            #pragma unroll
            for (int p=0;p<6;p++){ MMA(O[2*p],a,vh[p].x,vh[p].y); MMA(O[2*p+1],a,vh[p].z,vh[p].w); }
        }
        __syncthreads();                          // V buffer free
        if (c<31){ issueV(c+1); CP_COMMIT(); }
    }

    l0 += __shfl_xor_sync(0xffffffffu,l0,1); l0 += __shfl_xor_sync(0xffffffffu,l0,2);
    l1 += __shfl_xor_sync(0xffffffffu,l1,1); l1 += __shfl_xor_sync(0xffffffffu,l1,2);
    float inv0 = 1.0f/l0, inv1 = 1.0f/l1;
    const int t16 = b*128 + qt*4 + w;
    #pragma unroll
    for (int ktt=0;ktt<6;ktt++){
        float o00=O[2*ktt][0]*inv0,   o01=O[2*ktt][1]*inv0;
        float o10=O[2*ktt][2]*inv1,   o11=O[2*ktt][3]*inv1;
        float o20=O[2*ktt+1][0]*inv0, o21=O[2*ktt+1][1]*inv0;
        float o30=O[2*ktt+1][2]*inv1, o31=O[2*ktt+1][3]*inv1;
        uint4 hi, lo;
        hi.x=bfhi(o00,o01); hi.y=bfhi(o10,o11); hi.z=bfhi(o20,o21); hi.w=bfhi(o30,o31);
        lo.x=bflo(o00,o01,hi.x); lo.y=bflo(o10,o11,hi.y);
        lo.z=bflo(o20,o21,hi.z); lo.w=bflo(o30,o31,hi.w);
        size_t idx = ((size_t)t16*48 + h*6 + ktt)*32 + lane;
        g_oahi[idx]=hi; g_oalo[idx]=lo;
    }
}

// ---------------- Kernel 3: proj via mma; A AND B staged via cp.async 3-buf --
__global__ __launch_bounds__(256,2) void proj_kernel(
    const float* __restrict__ bu, float* __restrict__ y)
{
    __shared__ uint4 sB[3][256];   // [buf][plane(2) x ktpair(4) x lane(32)]
    __shared__ uint4 sA[3][512];   // [buf][warp(8) x plane(2) x lane(32)]
    const int tid = threadIdx.x, lane = tid&31, w = tid>>5;
    const int n0 = blockIdx.x*64;
    const int t16 = blockIdx.y*8 + w;
    const int bx4 = blockIdx.x*4;

    const uint4* Bsrc = (tid & 128) ? g_wulo : g_wuhi;
    const size_t boff = ((size_t)(bx4 + ((tid>>5)&3)))*32 + lane;
    const uint4* Ahsrc = g_oahi + (size_t)t16*48*32 + lane;
    const uint4* Alsrc = g_oalo + (size_t)t16*48*32 + lane;

    // one group = A-stage (2 CP16/thread) + B-stage (1 CP16/thread)
    auto issue = [&](int kt, int buf){
        CP16(smem_u32(&sA[buf][w*64 + lane]),      Ahsrc + (size_t)kt*32);
        CP16(smem_u32(&sA[buf][w*64 + 32 + lane]), Alsrc + (size_t)kt*32);
        CP16(smem_u32(&sB[buf][tid]),              Bsrc + (size_t)kt*1536 + boff);
    };

    float O[8][4];
    #pragma unroll
    for (int n=0;n<8;n++){
        #pragma unroll
        for (int i=0;i<4;i++) O[n][i]=0.f; }

    issue(0,0); CP_COMMIT();
    issue(1,1); CP_COMMIT();
    issue(2,2); CP_COMMIT();

    for (int kt=0; kt<48; kt++){
        if (kt==0)      CP_WAIT(2);
        else if (kt<47) CP_WAIT(1);
        else            CP_WAIT(0);
        __syncthreads();   // buffer kt%3 ready; buffer (kt-1)%3 reads done
        if (kt>=1 && kt+2<48){ issue(kt+2, (kt+2)%3); CP_COMMIT(); }

        const uint4* sa = sA[kt%3];
        const uint4* sb = sB[kt%3];
        uint4 ah = sa[w*64 + lane];
        uint4 al = sa[w*64 + 32 + lane];
        uint4 bhp[4], blp[4];
        #pragma unroll
        for (int p=0;p<4;p++){ bhp[p]=sb[p*32+lane]; blp[p]=sb[128+p*32+lane]; }

        #pragma unroll
        for (int p=0;p<4;p++){ MMA(O[2*p],ah,bhp[p].x,bhp[p].y); MMA(O[2*p+1],ah,bhp[p].z,bhp[p].w); }
        #pragma unroll
        for (int p=0;p<4;p++){ MMA(O[2*p],ah,blp[p].x,blp[p].y); MMA(O[2*p+1],ah,blp[p].z,blp[p].w); }
        #pragma unroll
        for (int p=0;p<4;p++){ MMA(O[2*p],al,bhp[p].x,bhp[p].y); MMA(O[2*p+1],al,bhp[p].z,bhp[p].w); }
    }

    const int gr=lane>>2, kk=(lane&3)*2;
    const int row0 = t16*16 + gr;
    #pragma unroll
    for (int nt=0;nt<8;nt++){
        int col = n0 + nt*8 + kk;
        float2 bv = *(const float2*)(bu + col);
        *(float2*)(y + (size_t)row0*768 + col)     = make_float2(O[nt][0]+bv.x, O[nt][1]+bv.y);
        *(float2*)(y + (size_t)(row0+8)*768 + col) = make_float2(O[nt][2]+bv.x, O[nt][3]+bv.y);
    }
}

extern "C" void kernel_launch(void* const* d_in, const int* in_sizes, int n_in,
                              void* d_out, int out_size)
{
    const float* x  = (const float*)d_in[0];
    const float* Wq = (const float*)d_in[1];
    const float* Wk = (const float*)d_in[2];
    const float* Wv = (const float*)d_in[3];
    const float* Wu = (const float*)d_in[4];
    const float* bu = (const float*)d_in[5];
    float* y = (float*)d_out;

    const int smem_qkv  = (6400 + 64*SSTR) * 4;  // 50688 B
    const int smem_attn = 4608 * 16;             // 73728 B -> 3 CTA/SM
    cudaFuncSetAttribute(qkv_kernel,  cudaFuncAttributeMaxDynamicSharedMemorySize, smem_qkv);
    cudaFuncSetAttribute(attn_kernel, cudaFuncAttributeMaxDynamicSharedMemorySize, smem_attn);

    const float inv4 = (float)(1.0/sqrt(sqrt(768.0)));
    const float qscale = inv4*inv4*1.4426950408889634f;  // inv4^2 * log2e, folded into Wq

    wprep_kernel<<<302, 256>>>(Wq, Wk, Wv, Wu, qscale);
    qkv_kernel<<<dim3(128,8), 256, smem_qkv>>>(x);
    attn_kernel<<<1024, 128, smem_attn>>>();
    proj_kernel<<<dim3(12,64), 256>>>(bu, y);
}

// round 16
// speedup vs baseline: 1.0488x; 1.0488x over previous
#include <cuda_runtime.h>
#include <cuda_bf16.h>
#include <cstdint>
#include <cmath>

#define BB 4
#define TT 2048
#define HH 8
#define DD 96
#define KDIM 768
#define BHN 32
#define SSTR 98

// Fragment-order scratch (uint4 per lane = two adjacent B-frags where paired)
__device__ uint4 g_qhi[BHN*128*6*32], g_qlo[BHN*128*6*32];   // Q A-frags [bh][t16][kt6][lane]
__device__ uint4 g_khi[BHN*32*6*4*32], g_klo[BHN*32*6*4*32]; // K B-fragpairs [bh][chunk][kt6][ktpair4][lane]
__device__ uint4 g_vhi[BHN*128*6*32], g_vlo[BHN*128*6*32];   // V B-fragpairs [bh][kt16][ndpair6][lane]
__device__ uint4 g_oahi[512*48*32], g_oalo[512*48*32];       // O A-frags [t16 512][kt48][lane]
__device__ uint4 g_wuhi[48*48*32], g_wulo[48*48*32];         // Wu B-fragpairs [kt48][ntpair48][lane]
__device__ uint4 g_wqh[108*32], g_wql[108*32];               // Wq/Wk/Wv B-fragpairs [mat3][kt6][ntpair6][lane]

__device__ __forceinline__ float fexp2(float x){ float y; asm("ex2.approx.ftz.f32 %0, %1;" : "=f"(y):"f"(x)); return y; }
__device__ __forceinline__ uint32_t smem_u32(const void* p){ uint32_t a; asm("{.reg .u64 t; cvta.to.shared.u64 t,%1; cvt.u32.u64 %0,t;}":"=r"(a):"l"(p)); return a; }

// pack (a,b) -> bf16x2 {lo16=a, hi16=b}
__device__ __forceinline__ uint32_t bfhi(float a, float b){
    uint32_t r; asm("cvt.rn.bf16x2.f32 %0, %1, %2;" : "=r"(r) : "f"(b), "f"(a)); return r;
}
__device__ __forceinline__ uint32_t bflo(float a, float b, uint32_t h){
    float ah = __uint_as_float(h<<16);
    float bh = __uint_as_float(h & 0xffff0000u);
    return bfhi(a-ah, b-bh);
}

#define MMA(D,A,B0,B1) asm volatile( \
  "mma.sync.aligned.m16n8k16.row.col.f32.bf16.bf16.f32 " \
  "{%0,%1,%2,%3}, {%4,%5,%6,%7}, {%8,%9}, {%0,%1,%2,%3};" \
  : "+f"((D)[0]), "+f"((D)[1]), "+f"((D)[2]), "+f"((D)[3]) \
  : "r"((A).x), "r"((A).y), "r"((A).z), "r"((A).w), "r"(B0), "r"(B1))

#define CP16(dst,src) asm volatile("cp.async.cg.shared.global [%0], [%1], 16;\n" :: "r"(dst), "l"(src))
#define CP_COMMIT()   asm volatile("cp.async.commit_group;\n" ::: "memory")
#define CP_WAIT(n)    asm volatile("cp.async.wait_group %0;\n" :: "n"(n) : "memory")

// ---------------- Kernel 0: all weights -> B-fragpair planes -----------------
__global__ __launch_bounds__(256) void wprep_kernel(
    const float* __restrict__ Wq, const float* __restrict__ Wk,
    const float* __restrict__ Wv, const float* __restrict__ Wu, float qscale)
{
    int wid = blockIdx.x*8 + (threadIdx.x>>5);
    int lane = threadIdx.x&31;
    if (wid < 2304){          // Wu: kt48 x ntpair48
        int kt = wid/48, ntp = wid - kt*48;
        int i = kt*16 + (lane&3)*2;
        int o0 = (2*ntp)*8 + (lane>>2);
        const float* r0 = Wu + (size_t)o0*768 + i;
        const float* r1 = r0 + 8*768;
        uint4 hi, lo;
        hi.x=bfhi(r0[0],r0[1]); hi.y=bfhi(r0[8],r0[9]);
        hi.z=bfhi(r1[0],r1[1]); hi.w=bfhi(r1[8],r1[9]);
        lo.x=bflo(r0[0],r0[1],hi.x); lo.y=bflo(r0[8],r0[9],hi.y);
        lo.z=bflo(r1[0],r1[1],hi.z); lo.w=bflo(r1[8],r1[9],hi.w);
        size_t idx = (size_t)wid*32 + lane;
        g_wuhi[idx]=hi; g_wulo[idx]=lo;
    } else if (wid < 2412){   // Wq/Wk/Wv: mat3 x kt6 x ntpair6
        int id = wid - 2304;
        int mat = id/36, r = id - mat*36;
        int kt = r/6, p = r - kt*6;
        const float* W = (mat==0)?Wq:(mat==1)?Wk:Wv;
        float s = (mat==0)? qscale : 1.0f;
        int i  = kt*16 + (lane&3)*2;
        int o0 = (2*p)*8 + (lane>>2);
        const float* r0 = W + (size_t)o0*96 + i;
        const float* r1 = r0 + 8*96;
        float a0=r0[0]*s, a1=r0[1]*s, b0=r0[8]*s, b1=r0[9]*s;
        float c0=r1[0]*s, c1=r1[1]*s, d0=r1[8]*s, d1=r1[9]*s;
        uint4 hi, lo;
        hi.x=bfhi(a0,a1); hi.y=bfhi(b0,b1);
        hi.z=bfhi(c0,c1); hi.w=bfhi(d0,d1);
        lo.x=bflo(a0,a1,hi.x); lo.y=bflo(b0,b1,hi.y);
        lo.z=bflo(c0,c1,hi.z); lo.w=bflo(d0,d1,hi.w);
        g_wqh[id*32+lane]=hi; g_wql[id*32+lane]=lo;
    }
}

// ---------------- Kernel 1: fused QKV projection via mma ---------------------
__global__ __launch_bounds__(256) void qkv_kernel(const float* __restrict__ x)
{
    extern __shared__ float sm1[];
    float* sX = sm1;            // [64][100]
    float* sS = sm1 + 6400;     // [64][SSTR] (V only)
    const int tid = threadIdx.x;
    const int h = blockIdx.y;
    const int t0g = blockIdx.x * 64;
    const int b = t0g >> 11, tl0 = t0g & 2047;
    const int bh = b*HH + h;

    for (int i=tid;i<1536;i+=256){ int r=i/24,q4=i-r*24;
        ((uint4*)sX)[r*25+q4] = *(const uint4*)(x + (size_t)(t0g+r)*768 + h*96 + q4*4); }
    __syncthreads();

    const int lane=tid&31, w=tid>>5;
    const int gr=lane>>2, kk=(lane&3)*2;
    const int rowb = (w&3)*16;
    const int pb   = (w>>2)*3;

    uint4 ah[6], al[6];
    #pragma unroll
    for (int kt=0;kt<6;kt++){
        const float* r0 = sX + (rowb+gr)*100 + kt*16 + kk;
        const float* r1 = r0 + 800;
        float a0=r0[0], a1=r0[1], b0=r1[0], b1=r1[1];
        float c0=r0[8], c1=r0[9], d0=r1[8], d1=r1[9];
        ah[kt].x=bfhi(a0,a1); ah[kt].y=bfhi(b0,b1);
        ah[kt].z=bfhi(c0,c1); ah[kt].w=bfhi(d0,d1);
        al[kt].x=bflo(a0,a1,ah[kt].x); al[kt].y=bflo(b0,b1,ah[kt].y);
        al[kt].z=bflo(c0,c1,ah[kt].z); al[kt].w=bflo(d0,d1,ah[kt].w);
    }

    #pragma unroll
    for (int mat=0; mat<3; mat++){
        float D[6][4];
        #pragma unroll
        for (int n=0;n<6;n++){
            #pragma unroll
            for (int i=0;i<4;i++) D[n][i]=0.f; }

        #pragma unroll
        for (int kt=0;kt<6;kt++){
            uint4 bh4[3], bl4[3];
            #pragma unroll
            for (int p=0;p<3;p++){
                int idx = (mat*36 + kt*6 + pb + p)*32 + lane;
                bh4[p]=g_wqh[idx]; bl4[p]=g_wql[idx];
            }
            uint4 a = ah[kt];
            #pragma unroll
            for (int p=0;p<3;p++){ MMA(D[2*p],a,bh4[p].x,bh4[p].y); MMA(D[2*p+1],a,bh4[p].z,bh4[p].w); }
            #pragma unroll
            for (int p=0;p<3;p++){ MMA(D[2*p],a,bl4[p].x,bl4[p].y); MMA(D[2*p+1],a,bl4[p].z,bl4[p].w); }
            a = al[kt];
            #pragma unroll
            for (int p=0;p<3;p++){ MMA(D[2*p],a,bh4[p].x,bh4[p].y); MMA(D[2*p+1],a,bh4[p].z,bh4[p].w); }
        }

        if (mat==0){
            size_t qi = ((size_t)(bh*128 + (tl0>>4) + (w&3))*6)*32 + lane;
            #pragma unroll
            for (int p=0;p<3;p++){
                int kt = pb + p;
                uint4 hi, lo;
                hi.x=bfhi(D[2*p][0],D[2*p][1]);     hi.y=bfhi(D[2*p][2],D[2*p][3]);
                hi.z=bfhi(D[2*p+1][0],D[2*p+1][1]); hi.w=bfhi(D[2*p+1][2],D[2*p+1][3]);
                lo.x=bflo(D[2*p][0],D[2*p][1],hi.x);     lo.y=bflo(D[2*p][2],D[2*p][3],hi.y);
                lo.z=bflo(D[2*p+1][0],D[2*p+1][1],hi.z); lo.w=bflo(D[2*p+1][2],D[2*p+1][3],hi.w);
                g_qhi[qi + kt*32]=hi; g_qlo[qi + kt*32]=lo;
            }
        } else if (mat==1){
            int chunk = tl0>>6, kp = w&3;
            size_t ki = ((size_t)(bh*32+chunk)*24)*32 + lane;
            #pragma unroll
            for (int p=0;p<3;p++){
                int kt = pb + p;
                uint4 hi, lo;
                hi.x=bfhi(D[2*p][0],D[2*p][1]);
                hi.y=bfhi(D[2*p+1][0],D[2*p+1][1]);
                hi.z=bfhi(D[2*p][2],D[2*p][3]);
                hi.w=bfhi(D[2*p+1][2],D[2*p+1][3]);
                lo.x=bflo(D[2*p][0],D[2*p][1],hi.x);     lo.y=bflo(D[2*p+1][0],D[2*p+1][1],hi.y);
                lo.z=bflo(D[2*p][2],D[2*p][3],hi.z);     lo.w=bflo(D[2*p+1][2],D[2*p+1][3],hi.w);
                g_khi[ki + (kt*4+kp)*32]=hi; g_klo[ki + (kt*4+kp)*32]=lo;
            }
        } else {
            #pragma unroll
            for (int ln=0;ln<6;ln++){
                int ng  = pb*2 + ln;
                int col = ng*8 + kk;
                int row = rowb + gr;
                *(float2*)(sS + row*SSTR + col)     = make_float2(D[ln][0], D[ln][1]);
                *(float2*)(sS + (row+8)*SSTR + col) = make_float2(D[ln][2], D[ln][3]);
            }
            __syncthreads();
            int ktile=w&3, plane=w>>2;
            const float* Rb = sS + (ktile*16+kk)*SSTR;
            uint4* dst = (plane?g_vlo:g_vhi) + ((size_t)(bh*128 + (tl0>>4) + ktile)*6)*32 + lane;
            #pragma unroll
            for (int p=0;p<6;p++){
                int d0=p*16+gr, d1=p*16+8+gr;
                uint4 u;
                uint32_t hx=bfhi(Rb[d0],Rb[SSTR+d0]), hy=bfhi(Rb[8*SSTR+d0],Rb[9*SSTR+d0]);
                uint32_t hz=bfhi(Rb[d1],Rb[SSTR+d1]), hw=bfhi(Rb[8*SSTR+d1],Rb[9*SSTR+d1]);
                if (plane){
                    u.x=bflo(Rb[d0],Rb[SSTR+d0],hx); u.y=bflo(Rb[8*SSTR+d0],Rb[9*SSTR+d0],hy);
                    u.z=bflo(Rb[d1],Rb[SSTR+d1],hz); u.w=bflo(Rb[8*SSTR+d1],Rb[9*SSTR+d1],hw);
                } else { u.x=hx; u.y=hy; u.z=hz; u.w=hw; }
                dst[p*32]=u;
            }
        }
    }
}

// ---------------- Kernel 2: FA2 mma.sync; K double-buf, V single-buf ---------
#define SHIFT 12.0f

__global__ __launch_bounds__(128,3) void attn_kernel()
{
    extern __shared__ uint4 sbuf[];
    const int tid = threadIdx.x, lane = tid&31, w = tid>>5;
    const int qt = blockIdx.x & 31, h = (blockIdx.x>>5)&7, b = blockIdx.x>>8;
    const int bh = b*HH + h;
    const uint32_t sb32 = smem_u32(sbuf);

    auto issueK = [&](int c, int buf){
        const uint4* pKh = g_khi + (size_t)(bh*32 + c)*768;
        const uint4* pKl = g_klo + (size_t)(bh*32 + c)*768;
        uint32_t base = sb32 + buf*24576;
        #pragma unroll
        for (int i=0;i<6;i++){
            int j = tid + i*128;
            CP16(base + j*16,       pKh + j);
            CP16(base + (768+j)*16, pKl + j);
        }
    };
    auto issueV = [&](int c){
        const uint4* pVh = g_vhi + (size_t)(bh*128 + c*4)*192;
        const uint4* pVl = g_vlo + (size_t)(bh*128 + c*4)*192;
        uint32_t base = sb32 + 49152;
        #pragma unroll
        for (int i=0;i<6;i++){
            int j = tid + i*128;
            CP16(base + j*16,       pVh + j);
            CP16(base + (768+j)*16, pVl + j);
        }
    };

    uint4 qh[6], ql[6];
    {
        const size_t qb = ((size_t)(bh*128 + qt*4 + w)*6)*32 + lane;
        #pragma unroll
        for (int kt=0;kt<6;kt++){ qh[kt]=g_qhi[qb+kt*32]; ql[kt]=g_qlo[qb+kt*32]; }
    }

    float O[12][4];
    #pragma unroll
    for (int n=0;n<12;n++){
        #pragma unroll
        for (int i=0;i<4;i++) O[n][i]=0.f; }
    float l0=0.f, l1=0.f;

    issueK(0,0); CP_COMMIT();
    issueV(0);   CP_COMMIT();
    issueK(1,1); CP_COMMIT();

    for (int c=0;c<32;c++){
        if (c<31) CP_WAIT(2); else CP_WAIT(1);    // K(c) ready
        __syncthreads();

        const uint4* Kb = sbuf + (c&1)*1536;
        const uint4* sKh4 = Kb;
        const uint4* sKl4 = Kb + 768;

        float S[8][4];
        #pragma unroll
        for (int n=0;n<8;n++){
            #pragma unroll
            for (int i=0;i<4;i++) S[n][i]=0.f; }
        #pragma unroll
        for (int kt=0;kt<6;kt++){
            uint4 kh[4], kl[4];
            #pragma unroll
            for (int p=0;p<4;p++){ kh[p]=sKh4[(kt*4+p)*32+lane]; kl[p]=sKl4[(kt*4+p)*32+lane]; }
            uint4 aq = qh[kt];
            #pragma unroll
            for (int p=0;p<4;p++){ MMA(S[2*p],aq,kh[p].x,kh[p].y); MMA(S[2*p+1],aq,kh[p].z,kh[p].w); }
            #pragma unroll
            for (int p=0;p<4;p++){ MMA(S[2*p],aq,kl[p].x,kl[p].y); MMA(S[2*p+1],aq,kl[p].z,kl[p].w); }
            aq = ql[kt];
            #pragma unroll
            for (int p=0;p<4;p++){ MMA(S[2*p],aq,kh[p].x,kh[p].y); MMA(S[2*p+1],aq,kh[p].z,kh[p].w); }
        }

        #pragma unroll
        for (int n=0;n<8;n++){
            S[n][0]=fexp2(S[n][0]-SHIFT); S[n][1]=fexp2(S[n][1]-SHIFT);
            S[n][2]=fexp2(S[n][2]-SHIFT); S[n][3]=fexp2(S[n][3]-SHIFT);
            l0 += S[n][0]+S[n][1]; l1 += S[n][2]+S[n][3];
        }

        uint4 ph[4], pl[4];
        #pragma unroll
        for (int ks=0;ks<4;ks++){
            ph[ks].x = bfhi(S[2*ks][0],  S[2*ks][1]);
            ph[ks].y = bfhi(S[2*ks][2],  S[2*ks][3]);
            ph[ks].z = bfhi(S[2*ks+1][0],S[2*ks+1][1]);
            ph[ks].w = bfhi(S[2*ks+1][2],S[2*ks+1][3]);
            pl[ks].x = bflo(S[2*ks][0],  S[2*ks][1],  ph[ks].x);
            pl[ks].y = bflo(S[2*ks][2],  S[2*ks][3],  ph[ks].y);
            pl[ks].z = bflo(S[2*ks+1][0],S[2*ks+1][1],ph[ks].z);
            pl[ks].w = bflo(S[2*ks+1][2],S[2*ks+1][3],ph[ks].w);
        }

        if (c<31) CP_WAIT(1); else CP_WAIT(0);    // V(c) ready
        __syncthreads();

        const uint4* sVh4 = sbuf + 3072;
        const uint4* sVl4 = sbuf + 3840;
        #pragma unroll
        for (int ks=0;ks<4;ks++){
            uint4 vh[6], vl[6];
            #pragma unroll
            for (int p=0;p<6;p++){ vh[p]=sVh4[(ks*6+p)*32+lane]; vl[p]=sVl4[(ks*6+p)*32+lane]; }
            uint4 a = ph[ks];
            #pragma unroll
            for (int p=0;p<6;p++){ MMA(O[2*p],a,vh[p].x,vh[p].y); MMA(O[2*p+1],a,vh[p].z,vh[p].w); }
            #pragma unroll
            for (int p=0;p<6;p++){ MMA(O[2*p],a,vl[p].x,vl[p].y); MMA(O[2*p+1],a,vl[p].z,vl[p].w); }
            a = pl[ks];
            #pragma unroll
            for (int p=0;p<6;p++){ MMA(O[2*p],a,vh[p].x,vh[p].y); MMA(O[2*p+1],a,vh[p].z,vh[p].w); }
        }
        __syncthreads();                          // V buffer free
        if (c<31){ issueV(c+1); CP_COMMIT(); }
        if (c<30){ issueK(c+2, c&1); CP_COMMIT(); }
    }

    l0 += __shfl_xor_sync(0xffffffffu,l0,1); l0 += __shfl_xor_sync(0xffffffffu,l0,2);
    l1 += __shfl_xor_sync(0xffffffffu,l1,1); l1 += __shfl_xor_sync(0xffffffffu,l1,2);
    float inv0 = 1.0f/l0, inv1 = 1.0f/l1;
    const int t16 = b*128 + qt*4 + w;
    #pragma unroll
    for (int ktt=0;ktt<6;ktt++){
        float o00=O[2*ktt][0]*inv0,   o01=O[2*ktt][1]*inv0;
        float o10=O[2*ktt][2]*inv1,   o11=O[2*ktt][3]*inv1;
        float o20=O[2*ktt+1][0]*inv0, o21=O[2*ktt+1][1]*inv0;
        float o30=O[2*ktt+1][2]*inv1, o31=O[2*ktt+1][3]*inv1;
        uint4 hi, lo;
        hi.x=bfhi(o00,o01); hi.y=bfhi(o10,o11); hi.z=bfhi(o20,o21); hi.w=bfhi(o30,o31);
        lo.x=bflo(o00,o01,hi.x); lo.y=bflo(o10,o11,hi.y);
        lo.z=bflo(o20,o21,hi.z); lo.w=bflo(o30,o31,hi.w);
        size_t idx = ((size_t)t16*48 + h*6 + ktt)*32 + lane;
        g_oahi[idx]=hi; g_oalo[idx]=lo;
    }
}

// ---------------- Kernel 3: proj via mma; B staged in smem (3-buf cp.async) --
__global__ __launch_bounds__(256,2) void proj_kernel(
    const float* __restrict__ bu, float* __restrict__ y)
{
    __shared__ uint4 sB[3][256];   // [buf][plane(2) x ktpair(4) x lane(32)]
    const int tid = threadIdx.x, lane = tid&31, w = tid>>5;
    const int n0 = blockIdx.x*64;
    const int t16 = blockIdx.y*8 + w;
    const int bx4 = blockIdx.x*4;

    const uint4* Bsrc = (tid & 128) ? g_wulo : g_wuhi;
    const size_t boff = ((size_t)(bx4 + ((tid>>5)&3)))*32 + lane;

    float O[8][4];
    #pragma unroll
    for (int n=0;n<8;n++){
        #pragma unroll
        for (int i=0;i<4;i++) O[n][i]=0.f; }

    const uint4* Ah = g_oahi + (size_t)t16*48*32 + lane;
    const uint4* Al = g_oalo + (size_t)t16*48*32 + lane;

    CP16(smem_u32(&sB[0][tid]), Bsrc + boff);            CP_COMMIT();
    CP16(smem_u32(&sB[1][tid]), Bsrc + 1536 + boff);     CP_COMMIT();
    CP16(smem_u32(&sB[2][tid]), Bsrc + 2*1536 + boff);   CP_COMMIT();

    uint4 ah = Ah[0], al = Al[0];

    for (int kt=0; kt<48; kt++){
        if (kt==0)      CP_WAIT(2);
        else if (kt<47) CP_WAIT(1);
        else            CP_WAIT(0);
        __syncthreads();   // buffer kt%3 ready; buffer (kt-1)%3 reads done
        if (kt>=1 && kt+2<48){
            CP16(smem_u32(&sB[(kt+2)%3][tid]), Bsrc + (size_t)(kt+2)*1536 + boff);
            CP_COMMIT();
        }
        uint4 ahn, aln;
        if (kt<47){ ahn = Ah[(kt+1)*32]; aln = Al[(kt+1)*32]; }

        const uint4* sb = sB[kt%3];
        uint4 bhp[4], blp[4];
        #pragma unroll
        for (int p=0;p<4;p++){ bhp[p]=sb[p*32+lane]; blp[p]=sb[128+p*32+lane]; }

        #pragma unroll
        for (int p=0;p<4;p++){ MMA(O[2*p],ah,bhp[p].x,bhp[p].y); MMA(O[2*p+1],ah,bhp[p].z,bhp[p].w); }
        #pragma unroll
        for (int p=0;p<4;p++){ MMA(O[2*p],ah,blp[p].x,blp[p].y); MMA(O[2*p+1],ah,blp[p].z,blp[p].w); }
        #pragma unroll
        for (int p=0;p<4;p++){ MMA(O[2*p],al,bhp[p].x,bhp[p].y); MMA(O[2*p+1],al,bhp[p].z,bhp[p].w); }

        if (kt<47){ ah=ahn; al=aln; }
    }

    const int gr=lane>>2, kk=(lane&3)*2;
    const int row0 = t16*16 + gr;
    #pragma unroll
    for (int nt=0;nt<8;nt++){
        int col = n0 + nt*8 + kk;
        float2 bv = *(const float2*)(bu + col);
        *(float2*)(y + (size_t)row0*768 + col)     = make_float2(O[nt][0]+bv.x, O[nt][1]+bv.y);
        *(float2*)(y + (size_t)(row0+8)*768 + col) = make_float2(O[nt][2]+bv.x, O[nt][3]+bv.y);
    }
}

extern "C" void kernel_launch(void* const* d_in, const int* in_sizes, int n_in,
                              void* d_out, int out_size)
{
    const float* x  = (const float*)d_in[0];
    const float* Wq = (const float*)d_in[1];
    const float* Wk = (const float*)d_in[2];
    const float* Wv = (const float*)d_in[3];
    const float* Wu = (const float*)d_in[4];
    const float* bu = (const float*)d_in[5];
    float* y = (float*)d_out;

    const int smem_qkv  = (6400 + 64*SSTR) * 4;  // 50688 B
    const int smem_attn = 4608 * 16;             // 73728 B -> 3 CTA/SM
    cudaFuncSetAttribute(qkv_kernel,  cudaFuncAttributeMaxDynamicSharedMemorySize, smem_qkv);
    cudaFuncSetAttribute(attn_kernel, cudaFuncAttributeMaxDynamicSharedMemorySize, smem_attn);

    const float inv4 = (float)(1.0/sqrt(sqrt(768.0)));
    const float qscale = inv4*inv4*1.4426950408889634f;  // inv4^2 * log2e, folded into Wq

    wprep_kernel<<<302, 256>>>(Wq, Wk, Wv, Wu, qscale);
    qkv_kernel<<<dim3(128,8), 256, smem_qkv>>>(x);
    attn_kernel<<<1024, 128, smem_attn>>>();
    proj_kernel<<<dim3(12,64), 256>>>(bu, y);
}